// round 9
// baseline (speedup 1.0000x reference)
#include <cuda_runtime.h>
#include <cuda_bf16.h>
#include <cstdint>

// Problem shapes (fixed by the dataset)
#define B_DIM 32
#define S_DIM 1024
#define H_DIM 384
#define MAXLEN 8192

// Output layout (flattened tuple, return order):
//   [0, B*MAXLEN*H)                      : out (float32)
//   [B*MAXLEN*H, +B)                     : mel_len (as float32)
//   [B*MAXLEN*H + B, +B*MAXLEN)          : mel_mask (as float32)
#define OFF_LEN   ((long long)B_DIM * MAXLEN * H_DIM)
#define OFF_MASK  (OFF_LEN + B_DIM)

// Scratch (no cudaMalloc allowed)
__device__ int g_cum[B_DIM * S_DIM];      // inclusive cumsum of durations
__device__ int g_mellen[B_DIM];           // total length per batch
__device__ int g_idx[B_DIM * MAXLEN];     // source token index per frame, -1 if invalid

// ---------------------------------------------------------------------------
// Kernel 1: per-batch inclusive scan of duration_target (S=1024, one block/batch)
// ---------------------------------------------------------------------------
__global__ void k_cumsum(const int* __restrict__ dur, float* __restrict__ out) {
    const int b   = blockIdx.x;
    const int tid = threadIdx.x;          // 0..1023
    int v = dur[b * S_DIM + tid];

    // warp inclusive scan
    const int lane = tid & 31;
    const int wid  = tid >> 5;
    #pragma unroll
    for (int d = 1; d < 32; d <<= 1) {
        int n = __shfl_up_sync(0xffffffffu, v, d);
        if (lane >= d) v += n;
    }

    __shared__ int warp_tot[32];
    if (lane == 31) warp_tot[wid] = v;
    __syncthreads();

    if (wid == 0) {
        int w = warp_tot[lane];
        #pragma unroll
        for (int d = 1; d < 32; d <<= 1) {
            int n = __shfl_up_sync(0xffffffffu, w, d);
            if (lane >= d) w += n;
        }
        warp_tot[lane] = w;
    }
    __syncthreads();

    if (wid > 0) v += warp_tot[wid - 1];
    g_cum[b * S_DIM + tid] = v;

    if (tid == S_DIM - 1) {
        g_mellen[b] = v;
        out[OFF_LEN + b] = (float)v;      // mel_len output (float32)
    }
}

// ---------------------------------------------------------------------------
// Kernel 2: searchsorted(cum, t, 'right') for every frame; also emit mel_mask
// grid = (MAXLEN/256, B), block = 256. cum row cached in shared.
//
// NOTE 1: upper_bound over 1024 elements has 1025 possible results -> needs
// ceil(log2(1025)) = 11 comparisons (10 was the R1-R5 rel_err=4e-2 bug).
// NOTE 2: bool inputs are stored as int32 by the harness (R6 fingerprint:
// rel_err = sqrt(3)/2 == exactly 3/4 of mask elements zero from reading
// int32 {01 00 00 00} bytes as uint8). Read masks as const int*.
// ---------------------------------------------------------------------------
__global__ void k_index(const int* __restrict__ mel_mask,
                        float* __restrict__ out) {
    const int b = blockIdx.y;
    __shared__ int s_cum[S_DIM];
    #pragma unroll
    for (int i = threadIdx.x; i < S_DIM; i += 256)
        s_cum[i] = g_cum[b * S_DIM + i];
    __syncthreads();

    const int t = blockIdx.x * 256 + threadIdx.x;   // frame index within MAXLEN
    const int mel_len = g_mellen[b];

    // upper_bound: first j with cum[j] > t  (11 iterations, see NOTE 1)
    int lo = 0, hi = S_DIM;
    #pragma unroll
    for (int it = 0; it < 11; ++it) {
        if (lo < hi) {
            int mid = (lo + hi) >> 1;
            if (s_cum[mid] <= t) lo = mid + 1; else hi = mid;
        }
    }
    int idx = lo < S_DIM ? lo : S_DIM - 1;

    const int fi = b * MAXLEN + t;
    g_idx[fi] = (t < mel_len) ? idx : -1;

    // mel_mask passthrough (int32-encoded bool -> float)
    out[OFF_MASK + fi] = mel_mask[fi] ? 1.0f : 0.0f;
}

// ---------------------------------------------------------------------------
// Kernel 3: gather. 4 frames per block, 96 float4 per frame (H=384 floats).
// blockDim = 384 (4 * 96). Pure streaming; HBM-bound.
// ---------------------------------------------------------------------------
__global__ void __launch_bounds__(384) k_gather(const float4* __restrict__ x4,
                                                float4* __restrict__ out4) {
    const int tid  = threadIdx.x;
    const int fl   = tid / 96;                 // frame within block (0..3)
    const int lane = tid - fl * 96;            // float4 lane within frame (0..95)
    const int f    = blockIdx.x * 4 + fl;      // global frame index
    const int b    = f >> 13;                  // MAXLEN = 2^13

    const int idx = g_idx[f];
    float4 v;
    if (idx >= 0) {
        v = x4[((long long)(b << 10) + idx) * 96 + lane];   // S=2^10
    } else {
        v = make_float4(0.f, 0.f, 0.f, 0.f);
    }
    out4[(long long)f * 96 + lane] = v;
}

// ---------------------------------------------------------------------------
extern "C" void kernel_launch(void* const* d_in, const int* in_sizes, int n_in,
                              void* d_out, int out_size) {
    // metadata order: x, src_mask, mel_mask, duration_target, pitch_target, max_len
    const float* x        = (const float*)d_in[0];
    const int*   mel_mask = (const int*)d_in[2];     // bool stored as int32
    const int*   dur      = (const int*)d_in[3];
    float* out = (float*)d_out;

    // 1) cumsum + mel_len
    k_cumsum<<<B_DIM, S_DIM>>>(dur, out);

    // 2) per-frame source index + mel_mask output
    {
        dim3 grid(MAXLEN / 256, B_DIM);
        k_index<<<grid, 256>>>(mel_mask, out);
    }

    // 3) main gather: B*MAXLEN frames, 4 per block
    {
        int nblocks = (B_DIM * MAXLEN) / 4;   // 65536
        k_gather<<<nblocks, 384>>>((const float4*)x, (float4*)out);
    }
}

// round 10
// speedup vs baseline: 1.2730x; 1.2730x over previous
#include <cuda_runtime.h>
#include <cuda_bf16.h>
#include <cstdint>

// Problem shapes (fixed by the dataset)
#define B_DIM 32
#define S_DIM 1024
#define H_DIM 384
#define MAXLEN 8192

// Output layout (flattened tuple, return order):
//   [0, B*MAXLEN*H)                      : out (float32)
//   [B*MAXLEN*H, +B)                     : mel_len (as float32)
//   [B*MAXLEN*H + B, +B*MAXLEN)          : mel_mask (as float32)
#define OFF_LEN   ((long long)B_DIM * MAXLEN * H_DIM)
#define OFF_MASK  (OFF_LEN + B_DIM)

// Scratch (no cudaMalloc allowed)
__device__ int g_idx[B_DIM * MAXLEN];     // source token index per frame, -1 if invalid

// ---------------------------------------------------------------------------
// Fused kernel: per-batch scan of durations + searchsorted for all frames +
// mel_len + mel_mask outputs. One block per batch (32 x 1024).
// Replaces R9's k_cumsum + k_index (7.5 us combined, g_cum round-trip)
// with one launch (~4.5 us predicted).
//
// NOTE 1: upper_bound over 1024 elements has 1025 possible results -> needs
// ceil(log2(1025)) = 11 comparisons (10 was the R1-R5 rel_err=4e-2 bug).
// NOTE 2: bool inputs are stored as int32 by the harness (R6 fingerprint:
// rel_err = sqrt(3)/2). Read masks as const int*.
// ---------------------------------------------------------------------------
__global__ void __launch_bounds__(1024) k_scan_index(
        const int* __restrict__ dur,
        const int* __restrict__ mel_mask,
        float* __restrict__ out) {
    const int b   = blockIdx.x;
    const int tid = threadIdx.x;          // 0..1023

    __shared__ int s_cum[S_DIM];
    __shared__ int s_warp[32];
    __shared__ int s_total;

    int v = dur[b * S_DIM + tid];

    // warp inclusive scan
    const int lane = tid & 31;
    const int wid  = tid >> 5;
    #pragma unroll
    for (int d = 1; d < 32; d <<= 1) {
        int n = __shfl_up_sync(0xffffffffu, v, d);
        if (lane >= d) v += n;
    }
    if (lane == 31) s_warp[wid] = v;
    __syncthreads();

    if (wid == 0) {
        int w = s_warp[lane];
        #pragma unroll
        for (int d = 1; d < 32; d <<= 1) {
            int n = __shfl_up_sync(0xffffffffu, w, d);
            if (lane >= d) w += n;
        }
        s_warp[lane] = w;
    }
    __syncthreads();

    if (wid > 0) v += s_warp[wid - 1];
    s_cum[tid] = v;

    if (tid == S_DIM - 1) {
        s_total = v;
        out[OFF_LEN + b] = (float)v;      // mel_len output (float32)
    }
    __syncthreads();

    const int mel_len = s_total;

    // 8 frames per thread (MAXLEN / 1024)
    #pragma unroll
    for (int it = 0; it < MAXLEN / 1024; ++it) {
        const int t = it * 1024 + tid;    // frame index within MAXLEN

        // upper_bound: first j with s_cum[j] > t  (11 iterations, NOTE 1)
        int lo = 0, hi = S_DIM;
        #pragma unroll
        for (int k = 0; k < 11; ++k) {
            if (lo < hi) {
                int mid = (lo + hi) >> 1;
                if (s_cum[mid] <= t) lo = mid + 1; else hi = mid;
            }
        }
        int idx = lo < S_DIM ? lo : S_DIM - 1;

        const int fi = b * MAXLEN + t;
        g_idx[fi] = (t < mel_len) ? idx : -1;

        // mel_mask passthrough (int32-encoded bool -> float)
        out[OFF_MASK + fi] = mel_mask[fi] ? 1.0f : 0.0f;
    }
}

// ---------------------------------------------------------------------------
// Gather: 8 frames per block, 2 frames per thread (MLP=2 on both the idx
// loads and the payload loads/stores). 96 float4 lanes per frame (H=384).
// blockDim = 384. Pure streaming; HBM-bound.
// ---------------------------------------------------------------------------
__global__ void __launch_bounds__(384) k_gather(const float4* __restrict__ x4,
                                                float4* __restrict__ out4) {
    const int tid  = threadIdx.x;
    const int fl   = tid / 96;                  // frame slot within block (0..3)
    const int lane = tid - fl * 96;             // float4 lane within frame (0..95)
    const int f0   = blockIdx.x * 8 + fl;       // first frame
    const int f1   = f0 + 4;                    // second frame (independent)

    // both idx loads issued back-to-back (independent -> MLP)
    const int idx0 = g_idx[f0];
    const int idx1 = g_idx[f1];

    const int b0 = f0 >> 13;                    // MAXLEN = 2^13
    const int b1 = f1 >> 13;

    float4 v0 = make_float4(0.f, 0.f, 0.f, 0.f);
    float4 v1 = make_float4(0.f, 0.f, 0.f, 0.f);
    if (idx0 >= 0) v0 = x4[((long long)(b0 << 10) + idx0) * 96 + lane];  // S=2^10
    if (idx1 >= 0) v1 = x4[((long long)(b1 << 10) + idx1) * 96 + lane];

    out4[(long long)f0 * 96 + lane] = v0;
    out4[(long long)f1 * 96 + lane] = v1;
}

// ---------------------------------------------------------------------------
extern "C" void kernel_launch(void* const* d_in, const int* in_sizes, int n_in,
                              void* d_out, int out_size) {
    // metadata order: x, src_mask, mel_mask, duration_target, pitch_target, max_len
    const float* x        = (const float*)d_in[0];
    const int*   mel_mask = (const int*)d_in[2];     // bool stored as int32
    const int*   dur      = (const int*)d_in[3];
    float* out = (float*)d_out;

    // 1) fused: cumsum + mel_len + per-frame index + mel_mask
    k_scan_index<<<B_DIM, 1024>>>(dur, mel_mask, out);

    // 2) main gather: B*MAXLEN frames, 8 per block, 2 per thread
    {
        int nblocks = (B_DIM * MAXLEN) / 8;   // 32768
        k_gather<<<nblocks, 384>>>((const float4*)x, (float4*)out);
    }
}

// round 11
// speedup vs baseline: 1.4080x; 1.1060x over previous
#include <cuda_runtime.h>
#include <cuda_bf16.h>
#include <cstdint>

// Problem shapes (fixed by the dataset)
#define B_DIM 32
#define S_DIM 1024
#define H_DIM 384
#define MAXLEN 8192

// Output layout (flattened tuple, return order):
//   [0, B*MAXLEN*H)                      : out (float32)
//   [B*MAXLEN*H, +B)                     : mel_len (as float32)
//   [B*MAXLEN*H + B, +B*MAXLEN)          : mel_mask (as float32)
#define OFF_LEN   ((long long)B_DIM * MAXLEN * H_DIM)
#define OFF_MASK  (OFF_LEN + B_DIM)

// Scratch (no cudaMalloc allowed)
__device__ int g_idx[B_DIM * MAXLEN];     // source token index per frame, -1 if invalid

// ---------------------------------------------------------------------------
// Kernel 1: per-batch scan of durations + searchsorted -> g_idx + mel_len.
// One block per batch (32 x 1024). Mask passthrough moved to k_gather (R10:
// 32 blocks were parallelism-starved writing 2 MB).
//
// NOTE 1: upper_bound over 1024 elements has 1025 possible results -> needs
// ceil(log2(1025)) = 11 comparisons (10 was the R1-R5 rel_err=4e-2 bug).
// NOTE 2: bool inputs are stored as int32 by the harness (R6 fingerprint:
// rel_err = sqrt(3)/2). Read masks as const int*.
// ---------------------------------------------------------------------------
__global__ void __launch_bounds__(1024) k_scan_index(
        const int* __restrict__ dur,
        float* __restrict__ out) {
    const int b   = blockIdx.x;
    const int tid = threadIdx.x;          // 0..1023

    __shared__ int s_cum[S_DIM];
    __shared__ int s_warp[32];
    __shared__ int s_total;

    int v = dur[b * S_DIM + tid];

    // warp inclusive scan
    const int lane = tid & 31;
    const int wid  = tid >> 5;
    #pragma unroll
    for (int d = 1; d < 32; d <<= 1) {
        int n = __shfl_up_sync(0xffffffffu, v, d);
        if (lane >= d) v += n;
    }
    if (lane == 31) s_warp[wid] = v;
    __syncthreads();

    if (wid == 0) {
        int w = s_warp[lane];
        #pragma unroll
        for (int d = 1; d < 32; d <<= 1) {
            int n = __shfl_up_sync(0xffffffffu, w, d);
            if (lane >= d) w += n;
        }
        s_warp[lane] = w;
    }
    __syncthreads();

    if (wid > 0) v += s_warp[wid - 1];
    s_cum[tid] = v;

    if (tid == S_DIM - 1) {
        s_total = v;
        out[OFF_LEN + b] = (float)v;      // mel_len output (float32)
    }
    __syncthreads();

    const int mel_len = s_total;

    // 8 frames per thread (MAXLEN / 1024)
    #pragma unroll
    for (int it = 0; it < MAXLEN / 1024; ++it) {
        const int t = it * 1024 + tid;    // frame index within MAXLEN

        // upper_bound: first j with s_cum[j] > t  (11 iterations, NOTE 1)
        int lo = 0, hi = S_DIM;
        #pragma unroll
        for (int k = 0; k < 11; ++k) {
            if (lo < hi) {
                int mid = (lo + hi) >> 1;
                if (s_cum[mid] <= t) lo = mid + 1; else hi = mid;
            }
        }
        int idx = lo < S_DIM ? lo : S_DIM - 1;

        g_idx[b * MAXLEN + t] = (t < mel_len) ? idx : -1;
    }
}

// ---------------------------------------------------------------------------
// Kernel 2: gather. 16 frames per block, 4 frames per thread (MLP=4 on idx
// loads, payload loads, and stores). 96 float4 lanes per frame (H=384).
// blockDim = 384. Streaming stores (__stcs) keep x resident in L2.
// Also emits the mel_mask passthrough (threads 0..15 handle the block's
// 16 frames).
// ---------------------------------------------------------------------------
__global__ void __launch_bounds__(384) k_gather(const float4* __restrict__ x4,
                                                const int* __restrict__ mel_mask,
                                                float4* __restrict__ out4,
                                                float* __restrict__ out) {
    const int tid  = threadIdx.x;
    const int fl   = tid / 96;                  // frame slot within block (0..3)
    const int lane = tid - fl * 96;             // float4 lane within frame (0..95)
    const int base = blockIdx.x * 16;

    int f[4], idx[4];
    #pragma unroll
    for (int i = 0; i < 4; ++i) {
        f[i]   = base + fl + i * 4;
        idx[i] = g_idx[f[i]];                   // 4 independent loads, front-batched
    }

    float4 v[4];
    #pragma unroll
    for (int i = 0; i < 4; ++i) {
        v[i] = make_float4(0.f, 0.f, 0.f, 0.f);
        if (idx[i] >= 0) {
            const int b = f[i] >> 13;           // MAXLEN = 2^13
            v[i] = x4[((long long)(b << 10) + idx[i]) * 96 + lane];  // S=2^10
        }
    }

    #pragma unroll
    for (int i = 0; i < 4; ++i)
        __stcs(&out4[(long long)f[i] * 96 + lane], v[i]);   // evict-first store

    // mel_mask passthrough: 16 frames per block, threads 0..15
    if (tid < 16) {
        const int fm = base + tid;
        out[OFF_MASK + fm] = mel_mask[fm] ? 1.0f : 0.0f;
    }
}

// ---------------------------------------------------------------------------
extern "C" void kernel_launch(void* const* d_in, const int* in_sizes, int n_in,
                              void* d_out, int out_size) {
    // metadata order: x, src_mask, mel_mask, duration_target, pitch_target, max_len
    const float* x        = (const float*)d_in[0];
    const int*   mel_mask = (const int*)d_in[2];     // bool stored as int32
    const int*   dur      = (const int*)d_in[3];
    float* out = (float*)d_out;

    // 1) scan + per-frame index + mel_len
    k_scan_index<<<B_DIM, 1024>>>(dur, out);

    // 2) main gather (+ mask passthrough): 16 frames per block, 4 per thread
    {
        int nblocks = (B_DIM * MAXLEN) / 16;   // 16384
        k_gather<<<nblocks, 384>>>((const float4*)x, mel_mask, (float4*)out, out);
    }
}

// round 14
// speedup vs baseline: 1.4772x; 1.0491x over previous
#include <cuda_runtime.h>
#include <cuda_bf16.h>
#include <cstdint>

// Problem shapes (fixed by the dataset)
#define B_DIM 32
#define S_DIM 1024
#define H_DIM 384
#define MAXLEN 8192

// Output layout (flattened tuple, return order):
//   [0, B*MAXLEN*H)                      : out (float32)
//   [B*MAXLEN*H, +B)                     : mel_len (as float32)
//   [B*MAXLEN*H + B, +B*MAXLEN)          : mel_mask (as float32)
#define OFF_LEN   ((long long)B_DIM * MAXLEN * H_DIM)
#define OFF_MASK  (OFF_LEN + B_DIM)

#define FRAMES_PER_BLOCK 32
#define BLOCKS_PER_BATCH (MAXLEN / FRAMES_PER_BLOCK)   // 256

// Scratch (no cudaMalloc allowed)
__device__ int g_cum[B_DIM * S_DIM];      // inclusive cumsum of durations

// ---------------------------------------------------------------------------
// Kernel 1: per-batch inclusive scan only (128 KB out). Index computation
// moved into the gather grid (R11: the 32-block scan kernel was a 7 us
// serial tail doing 8192 searches + 1 MB idx writes at 22% chip occupancy).
// ---------------------------------------------------------------------------
__global__ void __launch_bounds__(1024) k_scan(
        const int* __restrict__ dur,
        float* __restrict__ out) {
    const int b   = blockIdx.x;
    const int tid = threadIdx.x;          // 0..1023

    __shared__ int s_warp[32];

    int v = dur[b * S_DIM + tid];

    const int lane = tid & 31;
    const int wid  = tid >> 5;
    #pragma unroll
    for (int d = 1; d < 32; d <<= 1) {
        int n = __shfl_up_sync(0xffffffffu, v, d);
        if (lane >= d) v += n;
    }
    if (lane == 31) s_warp[wid] = v;
    __syncthreads();

    if (wid == 0) {
        int w = s_warp[lane];
        #pragma unroll
        for (int d = 1; d < 32; d <<= 1) {
            int n = __shfl_up_sync(0xffffffffu, w, d);
            if (lane >= d) w += n;
        }
        s_warp[lane] = w;
    }
    __syncthreads();

    if (wid > 0) v += s_warp[wid - 1];
    g_cum[b * S_DIM + tid] = v;

    if (tid == S_DIM - 1)
        out[OFF_LEN + b] = (float)v;      // mel_len output (float32)
}

// ---------------------------------------------------------------------------
// Kernel 2: fused index + gather + mask. 32 frames per block (one batch row
// chunk), 8 float4 per thread (MLP=8). blockDim = 384.
//   - stage the batch's 4 KB cum row into shared (g_cum is L2-resident)
//   - warp 0: 32 upper_bounds (11 LDS steps; NOTE 1) + mask passthrough
//   - all threads: 8 independent gathers, evict-first stores
//
// NOTE 1: upper_bound over 1024 elements has 1025 possible results -> needs
// ceil(log2(1025)) = 11 comparisons (10 was the R1-R5 rel_err=4e-2 bug).
// NOTE 2: bool inputs are stored as int32 by the harness (R6 fingerprint:
// rel_err = sqrt(3)/2). Read masks as const int*.
// ---------------------------------------------------------------------------
__global__ void __launch_bounds__(384) k_gather(const float4* __restrict__ x4,
                                                const int* __restrict__ mel_mask,
                                                float4* __restrict__ out4,
                                                float* __restrict__ out) {
    const int tid = threadIdx.x;
    const int b   = blockIdx.x / BLOCKS_PER_BATCH;
    const int t0  = (blockIdx.x % BLOCKS_PER_BATCH) * FRAMES_PER_BLOCK;

    __shared__ int s_cum[S_DIM];
    __shared__ int s_idx[FRAMES_PER_BLOCK];

    // stage cum row: 1024 ints over 384 threads (3 strided passes)
    #pragma unroll
    for (int i = tid; i < S_DIM; i += 384)
        s_cum[i] = g_cum[b * S_DIM + i];
    __syncthreads();

    // warp 0: searchsorted for this block's 32 frames + mask passthrough
    if (tid < FRAMES_PER_BLOCK) {
        const int t = t0 + tid;
        const int mel_len = s_cum[S_DIM - 1];

        int lo = 0, hi = S_DIM;
        #pragma unroll
        for (int k = 0; k < 11; ++k) {
            if (lo < hi) {
                int mid = (lo + hi) >> 1;
                if (s_cum[mid] <= t) lo = mid + 1; else hi = mid;
            }
        }
        int idx = lo < S_DIM ? lo : S_DIM - 1;
        s_idx[tid] = (t < mel_len) ? idx : -1;

        const int fm = b * MAXLEN + t;
        out[OFF_MASK + fm] = mel_mask[fm] ? 1.0f : 0.0f;
    }
    __syncthreads();

    const int fl   = tid / 96;                  // frame slot (0..3)
    const int lane = tid - fl * 96;             // float4 lane (0..95)
    const long long xbase = (long long)(b << 10) * 96;           // S=2^10
    const long long obase = ((long long)b * MAXLEN + t0) * 96;

    int idx[8];
    #pragma unroll
    for (int i = 0; i < 8; ++i)
        idx[i] = s_idx[fl + i * 4];

    float4 v[8];
    #pragma unroll
    for (int i = 0; i < 8; ++i) {
        v[i] = make_float4(0.f, 0.f, 0.f, 0.f);
        if (idx[i] >= 0)
            v[i] = x4[xbase + (long long)idx[i] * 96 + lane];
    }

    #pragma unroll
    for (int i = 0; i < 8; ++i)
        __stcs(&out4[obase + (long long)(fl + i * 4) * 96 + lane], v[i]);
}

// ---------------------------------------------------------------------------
extern "C" void kernel_launch(void* const* d_in, const int* in_sizes, int n_in,
                              void* d_out, int out_size) {
    // metadata order: x, src_mask, mel_mask, duration_target, pitch_target, max_len
    const float* x        = (const float*)d_in[0];
    const int*   mel_mask = (const int*)d_in[2];     // bool stored as int32
    const int*   dur      = (const int*)d_in[3];
    float* out = (float*)d_out;

    // 1) cumsum + mel_len only (~2 us)
    k_scan<<<B_DIM, 1024>>>(dur, out);

    // 2) fused index + gather + mask: 32 frames per block, 8 float4/thread
    {
        int nblocks = B_DIM * BLOCKS_PER_BATCH;   // 8192
        k_gather<<<nblocks, 384>>>((const float4*)x, mel_mask, (float4*)out, out);
    }
}